// round 13
// baseline (speedup 1.0000x reference)
#include <cuda_runtime.h>
#include <cuda_bf16.h>
#include <math.h>
#include <stdint.h>

#define N_IMG  128
#define N_REG  36
#define N_CAP  128
#define N_WORD 32
#define DIM    1024
#define LAMBDA 20.0f
#define EPSV   1e-8f
#define SLOPE  0.1f

#define M_TOT 4608              // 128*36
#define N_TOT 4096              // 128*32
#define KCAT  3072              // 3 * 1024 (hi/lo concat)
#define KB    (KCAT * 2)        // 6144 bytes per row
#define NK2   48                // KCAT / 64

// ---------------- scratch (static; no cudaMalloc allowed) ----------------
__device__ __align__(256) float         d_S[(size_t)M_TOT * N_TOT];     // 75.5MB
__device__ __align__(256) __nv_bfloat16 d_Acat[(size_t)M_TOT * KCAT];   // [Ah|Ah|Al]
__device__ __align__(256) __nv_bfloat16 d_Bcat[(size_t)N_TOT * KCAT];   // [Bh|Bl|Bh]
__device__ __align__(256) float d_Gi[N_IMG * N_REG * N_REG];
__device__ __align__(256) float d_Gc[N_CAP * N_WORD * N_WORD];

__device__ __forceinline__ float lrelu(float x) { return x > 0.f ? x : SLOPE * x; }

__device__ __forceinline__ uint32_t smem_u32(const void* p) {
    uint32_t a;
    asm("{ .reg .u64 t; cvta.to.shared.u64 t, %1; cvt.u32.u64 %0, t; }" : "=r"(a) : "l"(p));
    return a;
}

#define LDSM4(r0, r1, r2, r3, addr) \
    asm volatile("ldmatrix.sync.aligned.m8n8.x4.shared.b16 {%0,%1,%2,%3}, [%4];" \
        : "=r"(r0), "=r"(r1), "=r"(r2), "=r"(r3) : "r"(addr))

#define MMA16816(d, a, b) \
    asm volatile("mma.sync.aligned.m16n8k16.row.col.f32.bf16.bf16.f32 " \
        "{%0,%1,%2,%3}, {%4,%5,%6,%7}, {%8,%9}, {%0,%1,%2,%3};" \
        : "+f"((d)[0]), "+f"((d)[1]), "+f"((d)[2]), "+f"((d)[3]) \
        : "r"((a)[0]), "r"((a)[1]), "r"((a)[2]), "r"((a)[3]), "r"((b)[0]), "r"((b)[1]))

#define CP16(dst, src) \
    asm volatile("cp.async.cg.shared.global [%0], [%1], 16;" :: "r"(dst), "l"(src))

// ---------------------------------------------------------------------------
// prep (vectorized): fp32 -> bf16 hi/lo concat, 2 elements per thread.
// ---------------------------------------------------------------------------
__global__ void prep_kernel(const float* __restrict__ X, int totalPairs, int sel) {
    int p = blockIdx.x * blockDim.x + threadIdx.x;
    if (p >= totalPairs) return;
    float2 v = *(const float2*)(X + 2 * (size_t)p);
    __nv_bfloat16 h0 = __float2bfloat16(v.x);
    __nv_bfloat16 h1 = __float2bfloat16(v.y);
    __nv_bfloat16 l0 = __float2bfloat16(v.x - __bfloat162float(h0));
    __nv_bfloat16 l1 = __float2bfloat16(v.y - __bfloat162float(h1));
    uint32_t hh = ((uint32_t)*(uint16_t*)&h1 << 16) | *(uint16_t*)&h0;
    uint32_t ll = ((uint32_t)*(uint16_t*)&l1 << 16) | *(uint16_t*)&l0;
    int row = p >> 9, kp = p & 511;
    uint32_t* out = (uint32_t*)(sel ? d_Bcat : d_Acat);
    size_t base = (size_t)row * (KCAT / 2) + kp;
    out[base] = hh;
    out[base + 512]  = sel ? ll : hh;
    out[base + 1024] = sel ? hh : ll;
}

// ---------------------------------------------------------------------------
// bf16 mma.sync GEMM (round-10 config): S = Acat @ Bcat^T, fp32 accum.
// CTA 128x128, BK=64, 3-stage cp.async, 4 warps (2m x 2n), warp tile 64x64,
// 2 CTAs/SM, fragment double-buffering across ks steps.
// ---------------------------------------------------------------------------
#define APITCH 144
#define ASTAGE (128 * APITCH)          // 18432
#define GSTAGE (2 * ASTAGE)            // 36864
#define GEMM_SMEM (3 * GSTAGE)         // 110592

__global__ __launch_bounds__(128, 2)
void gemm_kernel() {
    extern __shared__ char smem[];
    const uint32_t sb = smem_u32(smem);
    const int tid  = threadIdx.x;
    const int lane = tid & 31;
    const int wid  = tid >> 5;
    const int wm   = wid & 1;
    const int wn   = wid >> 1;
    const int mb   = blockIdx.y * 128;
    const int nb   = blockIdx.x * 128;

    const char* Ag = (const char*)d_Acat + (size_t)mb * KB;
    const char* Bg = (const char*)d_Bcat + (size_t)nb * KB;

    float acc[4][8][4];
#pragma unroll
    for (int i = 0; i < 4; i++)
#pragma unroll
        for (int j = 0; j < 8; j++)
#pragma unroll
            for (int q = 0; q < 4; q++) acc[i][j][q] = 0.f;

    auto load_stage = [&](int s, int kt) {
        const uint32_t sA = sb + s * GSTAGE;
        const uint32_t sB = sA + ASTAGE;
        const char* Asrc = Ag + kt * 128;
        const char* Bsrc = Bg + kt * 128;
#pragma unroll
        for (int i = 0; i < 8; i++) {
            int idx = tid + i * 128;
            int row = idx >> 3, seg = idx & 7;
            CP16(sA + row * APITCH + seg * 16, Asrc + (size_t)row * KB + seg * 16);
        }
#pragma unroll
        for (int i = 0; i < 8; i++) {
            int idx = tid + i * 128;
            int row = idx >> 3, seg = idx & 7;
            CP16(sB + row * APITCH + seg * 16, Bsrc + (size_t)row * KB + seg * 16);
        }
    };

    load_stage(0, 0);
    asm volatile("cp.async.commit_group;" ::: "memory");
    load_stage(1, 1);
    asm volatile("cp.async.commit_group;" ::: "memory");

    const uint32_t aoff = (uint32_t)((wm * 64 + (lane & 15)) * APITCH + (lane >> 4) * 16);
    const uint32_t boff = (uint32_t)((wn * 64 + (lane & 7) + ((lane >> 4) & 1) * 8) * APITCH
                                     + ((lane >> 3) & 1) * 16);

    uint32_t af[2][4][4];
    uint32_t bf[2][8][2];

    auto ldsm_ks = [&](uint32_t sA, uint32_t sB, int ks, int buf) {
        const uint32_t kbyte = (uint32_t)ks * 32;
#pragma unroll
        for (int mi = 0; mi < 4; mi++)
            LDSM4(af[buf][mi][0], af[buf][mi][1], af[buf][mi][2], af[buf][mi][3],
                  sA + aoff + mi * (16 * APITCH) + kbyte);
#pragma unroll
        for (int nt = 0; nt < 4; nt++) {
            uint32_t r0, r1, r2, r3;
            LDSM4(r0, r1, r2, r3, sB + boff + nt * (16 * APITCH) + kbyte);
            bf[buf][2 * nt][0] = r0;     bf[buf][2 * nt][1] = r1;
            bf[buf][2 * nt + 1][0] = r2; bf[buf][2 * nt + 1][1] = r3;
        }
    };

    for (int kt = 0; kt < NK2; kt++) {
        const int s = kt % 3;
        asm volatile("cp.async.wait_group 1;" ::: "memory");
        __syncthreads();
        if (kt + 2 < NK2) load_stage((kt + 2) % 3, kt + 2);
        asm volatile("cp.async.commit_group;" ::: "memory");

        const uint32_t sA = sb + s * GSTAGE;
        const uint32_t sB = sA + ASTAGE;
        ldsm_ks(sA, sB, 0, 0);
#pragma unroll
        for (int ks = 0; ks < 4; ks++) {
            const int cur = ks & 1;
            if (ks < 3) ldsm_ks(sA, sB, ks + 1, cur ^ 1);
#pragma unroll
            for (int mi = 0; mi < 4; mi++)
#pragma unroll
                for (int nj = 0; nj < 8; nj++)
                    MMA16816(acc[mi][nj], af[cur][mi], bf[cur][nj]);
        }
    }
    asm volatile("cp.async.wait_group 0;" ::: "memory");

#pragma unroll
    for (int mi = 0; mi < 4; mi++) {
#pragma unroll
        for (int nj = 0; nj < 8; nj++) {
            int row = mb + wm * 64 + mi * 16 + (lane >> 2);
            int col = nb + wn * 64 + nj * 8 + (lane & 3) * 2;
            float* p0 = d_S + (size_t)row * N_TOT + col;
            float* p1 = d_S + (size_t)(row + 8) * N_TOT + col;
            *(float2*)p0 = make_float2(acc[mi][nj][0], acc[mi][nj][1]);
            *(float2*)p1 = make_float2(acc[mi][nj][2], acc[mi][nj][3]);
        }
    }
}

// ---------------------------------------------------------------------------
// gram3: G = X X^T per item, float4-vectorized inner loop.
// ---------------------------------------------------------------------------
__global__ __launch_bounds__(256)
void gram2_kernel(const float* __restrict__ imgs, const float* __restrict__ caps) {
    const int item = blockIdx.x;
    const bool isCap = item >= N_IMG;
    const float* X = isCap ? caps + (size_t)(item - N_IMG) * N_WORD * DIM
                           : imgs + (size_t)item * N_REG * DIM;
    const int R = isCap ? N_WORD : N_REG;

    __shared__ __align__(16) float xs[36][260];
    const int tid = threadIdx.x;
    const int tr = (tid % 12) * 3;
    const int tc = (tid / 12) * 2;
    const bool act = tid < 216;

    float acc00 = 0.f, acc01 = 0.f, acc10 = 0.f, acc11 = 0.f, acc20 = 0.f, acc21 = 0.f;

    for (int k0 = 0; k0 < DIM; k0 += 256) {
        __syncthreads();
        for (int idx = tid; idx < 36 * 64; idx += 256) {
            int r = idx >> 6, kq = idx & 63;
            float4 v = (r < R) ? ((const float4*)(X + (size_t)r * DIM + k0))[kq]
                               : make_float4(0.f, 0.f, 0.f, 0.f);
            *(float4*)&xs[r][kq * 4] = v;
        }
        __syncthreads();
        if (act) {
            const float4* A0 = (const float4*)xs[tr];
            const float4* A1 = (const float4*)xs[tr + 1];
            const float4* A2 = (const float4*)xs[tr + 2];
            const float4* B0 = (const float4*)xs[tc];
            const float4* B1 = (const float4*)xs[tc + 1];
#pragma unroll 8
            for (int kq = 0; kq < 64; kq++) {
                float4 a0 = A0[kq], a1 = A1[kq], a2 = A2[kq];
                float4 b0 = B0[kq], b1 = B1[kq];
                acc00 += a0.x * b0.x + a0.y * b0.y + a0.z * b0.z + a0.w * b0.w;
                acc01 += a0.x * b1.x + a0.y * b1.y + a0.z * b1.z + a0.w * b1.w;
                acc10 += a1.x * b0.x + a1.y * b0.y + a1.z * b0.z + a1.w * b0.w;
                acc11 += a1.x * b1.x + a1.y * b1.y + a1.z * b1.z + a1.w * b1.w;
                acc20 += a2.x * b0.x + a2.y * b0.y + a2.z * b0.z + a2.w * b0.w;
                acc21 += a2.x * b1.x + a2.y * b1.y + a2.z * b1.z + a2.w * b1.w;
            }
        }
    }
    if (act) {
        float* G = isCap ? d_Gc + (size_t)(item - N_IMG) * (N_WORD * N_WORD)
                         : d_Gi + (size_t)item * (N_REG * N_REG);
        float v[3][2] = {{acc00, acc01}, {acc10, acc11}, {acc20, acc21}};
#pragma unroll
        for (int i = 0; i < 3; i++)
#pragma unroll
            for (int j = 0; j < 2; j++) {
                int r = tr + i, c2 = tc + j;
                if (r < R && c2 < R) G[r * R + c2] = v[i][j];
            }
    }
}

// ---------------------------------------------------------------------------
// attention v8: one CTA per (image, caption), 160 threads (5 warps).
// 2 lanes per query: both lanes redundantly compute the weight vector a[]
// (registers), then split the quadratic form by even/odd rows and combine
// with one shfl. Warps 0-1: t2i (32 words). Warps 2-4: i2t (36 regions).
// ---------------------------------------------------------------------------
__global__ __launch_bounds__(160, 3)
void attn_kernel(float* __restrict__ out) {
    const int i = blockIdx.x, c = blockIdx.y, tid = threadIdx.x;

    __shared__ __align__(16) float Ss[36][36];
    __shared__ __align__(16) float Gi[36][40];
    __shared__ __align__(16) float Gc[32][32];
    __shared__ float irn_t[36], irn_i[32];
    __shared__ float red[5];

    const float4* Sblk4 = (const float4*)(d_S + (size_t)(i * N_REG) * N_TOT + c * N_WORD);
    const size_t srow4 = N_TOT / 4;
    for (int idx = tid; idx < 36 * 8; idx += 160) {
        int r = idx >> 3, q = idx & 7;
        *(float4*)&Ss[r][q * 4] = Sblk4[(size_t)r * srow4 + q];
    }
    const float4* gi4 = (const float4*)(d_Gi + (size_t)i * (36 * 36));
    for (int idx = tid; idx < 324; idx += 160) {
        int e = idx * 4, r = e / 36, col = e - r * 36;
        *(float4*)&Gi[r][col] = gi4[idx];
    }
    const float4* gc4 = (const float4*)(d_Gc + (size_t)c * (32 * 32));
    for (int idx = tid; idx < 256; idx += 160) {
        ((float4*)Gc)[idx] = gc4[idx];
    }
    __syncthreads();

    // --- norms of lrelu(S): rows (t2i) and cols (i2t) ---
    if (tid < 36) {
        float s0 = 0.f, s1 = 0.f;
#pragma unroll
        for (int w = 0; w < 32; w += 2) {
            float v0 = lrelu(Ss[tid][w]);     s0 += v0 * v0;
            float v1 = lrelu(Ss[tid][w + 1]); s1 += v1 * v1;
        }
        irn_t[tid] = __fdividef(1.f, sqrtf(s0 + s1) + EPSV);
    } else if (tid < 68) {
        int w = tid - 36;
        float s0 = 0.f, s1 = 0.f;
#pragma unroll
        for (int r = 0; r < 36; r += 2) {
            float v0 = lrelu(Ss[r][w]);     s0 += v0 * v0;
            float v1 = lrelu(Ss[r + 1][w]); s1 += v1 * v1;
        }
        irn_i[w] = __fdividef(1.f, sqrtf(s0 + s1) + EPSV);
    }
    __syncthreads();

    const int wid = tid >> 5, lane = tid & 31;
    float val = 0.f;

    if (wid < 2) {
        // ---- t2i: 2 lanes per word; w = tid/2, h = tid&1 ----
        const int w = tid >> 1;
        const int h = tid & 1;
        float a[36];
        float mx = -1e30f;
#pragma unroll
        for (int r = 0; r < 36; r++) {
            float v = lrelu(Ss[r][w]) * irn_t[r];
            a[r] = v; mx = fmaxf(mx, v);
        }
        float esum = 0.f;
#pragma unroll
        for (int r = 0; r < 36; r++) { float e = __expf(LAMBDA * (a[r] - mx)); a[r] = e; esum += e; }
        float th = esum * (1.f / 36.f), tsum = 0.f;
#pragma unroll
        for (int r = 0; r < 36; r++) { float v = (a[r] > th) ? a[r] : 0.f; a[r] = v; tsum += v; }
        float inv = __fdividef(1.f, tsum), num = 0.f;
#pragma unroll
        for (int r = 0; r < 36; r++) { a[r] *= inv; num += a[r] * Ss[r][w]; }
        // quadratic form: rows h, h+2, ... (18 rows per lane), combine via shfl
        float den = 0.f;
#pragma unroll
        for (int rr = 0; rr < 18; rr++) {
            const int r = 2 * rr + h;
            const float4* Gr = (const float4*)Gi[r];
            float y0 = 0.f, y1 = 0.f, y2 = 0.f, y3 = 0.f;
#pragma unroll
            for (int q = 0; q < 9; q++) {
                float4 g = Gr[q];
                y0 += g.x * a[4 * q + 0];
                y1 += g.y * a[4 * q + 1];
                y2 += g.z * a[4 * q + 2];
                y3 += g.w * a[4 * q + 3];
            }
            den += a[r] * ((y0 + y1) + (y2 + y3));
        }
        den += __shfl_xor_sync(0xFFFFFFFFu, den, 1);
        if (h == 0)
            val = num * __fdividef(1.f,
                  fmaxf(sqrtf(Gc[w][w]), EPSV) * fmaxf(sqrtf(den), EPSV)) * (1.f / 32.f);
    } else {
        // ---- i2t: 2 lanes per region; p = (tid-64)/2, h = (tid-64)&1 ----
        const int t = tid - 64;
        const int p = t >> 1;
        const int h = t & 1;
        const bool valid = p < 36;
        const int r = valid ? p : 35;
        float a[32];
        float mx = -1e30f;
#pragma unroll
        for (int w = 0; w < 32; w++) {
            float v = lrelu(Ss[r][w]) * irn_i[w];
            a[w] = v; mx = fmaxf(mx, v);
        }
        float esum = 0.f;
#pragma unroll
        for (int w = 0; w < 32; w++) { float e = __expf(LAMBDA * (a[w] - mx)); a[w] = e; esum += e; }
        float th = esum * (1.f / 32.f), tsum = 0.f;
#pragma unroll
        for (int w = 0; w < 32; w++) { float v = (a[w] > th) ? a[w] : 0.f; a[w] = v; tsum += v; }
        float inv = __fdividef(1.f, tsum), num = 0.f;
#pragma unroll
        for (int w = 0; w < 32; w++) { a[w] *= inv; num += a[w] * Ss[r][w]; }
        float den = 0.f;
#pragma unroll
        for (int ww = 0; ww < 16; ww++) {
            const int w = 2 * ww + h;
            const float4* Gr = (const float4*)Gc[w];
            float y0 = 0.f, y1 = 0.f, y2 = 0.f, y3 = 0.f;
#pragma unroll
            for (int q = 0; q < 8; q++) {
                float4 g = Gr[q];
                y0 += g.x * a[4 * q + 0];
                y1 += g.y * a[4 * q + 1];
                y2 += g.z * a[4 * q + 2];
                y3 += g.w * a[4 * q + 3];
            }
            den += a[w] * ((y0 + y1) + (y2 + y3));
        }
        den += __shfl_xor_sync(0xFFFFFFFFu, den, 1);
        if (valid && h == 0)
            val = num * __fdividef(1.f,
                  fmaxf(sqrtf(Gi[r][r]), EPSV) * fmaxf(sqrtf(den), EPSV)) * (1.f / 36.f);
    }

    // warp-level sum, then cross-warp
#pragma unroll
    for (int off = 16; off > 0; off >>= 1)
        val += __shfl_xor_sync(0xFFFFFFFFu, val, off);
    if (lane == 0) red[wid] = val;
    __syncthreads();
    if (tid == 0)
        out[i * N_CAP + c] = red[0] + red[1] + red[2] + red[3] + red[4];
}

// ---------------------------------------------------------------------------
extern "C" void kernel_launch(void* const* d_in, const int* in_sizes, int n_in,
                              void* d_out, int out_size) {
    const float* images   = (const float*)d_in[0];   // (128,36,1024)
    const float* captions = (const float*)d_in[1];   // (128,32,1024)
    float* out = (float*)d_out;                       // (128,128)

    prep_kernel<<<(M_TOT * DIM / 2) / 256, 256>>>(images, M_TOT * DIM / 2, 0);
    prep_kernel<<<(N_TOT * DIM / 2) / 256, 256>>>(captions, N_TOT * DIM / 2, 1);
    gram2_kernel<<<256, 256>>>(images, captions);

    cudaFuncSetAttribute(gemm_kernel, cudaFuncAttributeMaxDynamicSharedMemorySize, GEMM_SMEM);
    dim3 ggrid(N_TOT / 128, M_TOT / 128);   // (32, 36)
    gemm_kernel<<<ggrid, 128, GEMM_SMEM>>>();

    dim3 agrid(N_IMG, N_CAP);
    attn_kernel<<<agrid, 160>>>(out);
}

// round 14
// speedup vs baseline: 1.0707x; 1.0707x over previous
#include <cuda_runtime.h>
#include <cuda_bf16.h>
#include <math.h>
#include <stdint.h>

#define N_IMG  128
#define N_REG  36
#define N_CAP  128
#define N_WORD 32
#define DIM    1024
#define LAMBDA 20.0f
#define EPSV   1e-8f
#define SLOPE  0.1f

#define M_TOT 4608              // 128*36
#define N_TOT 4096              // 128*32
#define KCAT  3072              // 3 * 1024 (hi/lo concat)
#define KB    (KCAT * 2)        // 6144 bytes per row
#define NK2   48                // KCAT / 64

// ---------------- scratch (static; no cudaMalloc allowed) ----------------
__device__ __align__(256) float         d_S[(size_t)M_TOT * N_TOT];     // 75.5MB
__device__ __align__(256) __nv_bfloat16 d_Acat[(size_t)M_TOT * KCAT];   // [Ah|Ah|Al]
__device__ __align__(256) __nv_bfloat16 d_Bcat[(size_t)N_TOT * KCAT];   // [Bh|Bl|Bh]
__device__ __align__(256) float d_Gi[N_IMG * N_REG * N_REG];
__device__ __align__(256) float d_Gc[N_CAP * N_WORD * N_WORD];

__device__ __forceinline__ float lrelu(float x) { return x > 0.f ? x : SLOPE * x; }

__device__ __forceinline__ uint32_t smem_u32(const void* p) {
    uint32_t a;
    asm("{ .reg .u64 t; cvta.to.shared.u64 t, %1; cvt.u32.u64 %0, t; }" : "=r"(a) : "l"(p));
    return a;
}

#define LDSM4(r0, r1, r2, r3, addr) \
    asm volatile("ldmatrix.sync.aligned.m8n8.x4.shared.b16 {%0,%1,%2,%3}, [%4];" \
        : "=r"(r0), "=r"(r1), "=r"(r2), "=r"(r3) : "r"(addr))

#define MMA16816(d, a, b) \
    asm volatile("mma.sync.aligned.m16n8k16.row.col.f32.bf16.bf16.f32 " \
        "{%0,%1,%2,%3}, {%4,%5,%6,%7}, {%8,%9}, {%0,%1,%2,%3};" \
        : "+f"((d)[0]), "+f"((d)[1]), "+f"((d)[2]), "+f"((d)[3]) \
        : "r"((a)[0]), "r"((a)[1]), "r"((a)[2]), "r"((a)[3]), "r"((b)[0]), "r"((b)[1]))

#define CP16(dst, src) \
    asm volatile("cp.async.cg.shared.global [%0], [%1], 16;" :: "r"(dst), "l"(src))

// ---------------------------------------------------------------------------
// prep (vectorized): fp32 -> bf16 hi/lo concat, 2 elements per thread.
// ---------------------------------------------------------------------------
__global__ void prep_kernel(const float* __restrict__ X, int totalPairs, int sel) {
    int p = blockIdx.x * blockDim.x + threadIdx.x;
    if (p >= totalPairs) return;
    float2 v = *(const float2*)(X + 2 * (size_t)p);
    __nv_bfloat16 h0 = __float2bfloat16(v.x);
    __nv_bfloat16 h1 = __float2bfloat16(v.y);
    __nv_bfloat16 l0 = __float2bfloat16(v.x - __bfloat162float(h0));
    __nv_bfloat16 l1 = __float2bfloat16(v.y - __bfloat162float(h1));
    uint32_t hh = ((uint32_t)*(uint16_t*)&h1 << 16) | *(uint16_t*)&h0;
    uint32_t ll = ((uint32_t)*(uint16_t*)&l1 << 16) | *(uint16_t*)&l0;
    int row = p >> 9, kp = p & 511;
    uint32_t* out = (uint32_t*)(sel ? d_Bcat : d_Acat);
    size_t base = (size_t)row * (KCAT / 2) + kp;
    out[base] = hh;
    out[base + 512]  = sel ? ll : hh;
    out[base + 1024] = sel ? hh : ll;
}

// ---------------------------------------------------------------------------
// bf16 mma.sync GEMM (round-10 config): S = Acat @ Bcat^T, fp32 accum.
// CTA 128x128, BK=64, 3-stage cp.async, 4 warps (2m x 2n), warp tile 64x64,
// 2 CTAs/SM, fragment double-buffering across ks steps.
// ---------------------------------------------------------------------------
#define APITCH 144
#define ASTAGE (128 * APITCH)          // 18432
#define GSTAGE (2 * ASTAGE)            // 36864
#define GEMM_SMEM (3 * GSTAGE)         // 110592

__global__ __launch_bounds__(128, 2)
void gemm_kernel() {
    extern __shared__ char smem[];
    const uint32_t sb = smem_u32(smem);
    const int tid  = threadIdx.x;
    const int lane = tid & 31;
    const int wid  = tid >> 5;
    const int wm   = wid & 1;
    const int wn   = wid >> 1;
    const int mb   = blockIdx.y * 128;
    const int nb   = blockIdx.x * 128;

    const char* Ag = (const char*)d_Acat + (size_t)mb * KB;
    const char* Bg = (const char*)d_Bcat + (size_t)nb * KB;

    float acc[4][8][4];
#pragma unroll
    for (int i = 0; i < 4; i++)
#pragma unroll
        for (int j = 0; j < 8; j++)
#pragma unroll
            for (int q = 0; q < 4; q++) acc[i][j][q] = 0.f;

    auto load_stage = [&](int s, int kt) {
        const uint32_t sA = sb + s * GSTAGE;
        const uint32_t sB = sA + ASTAGE;
        const char* Asrc = Ag + kt * 128;
        const char* Bsrc = Bg + kt * 128;
#pragma unroll
        for (int i = 0; i < 8; i++) {
            int idx = tid + i * 128;
            int row = idx >> 3, seg = idx & 7;
            CP16(sA + row * APITCH + seg * 16, Asrc + (size_t)row * KB + seg * 16);
        }
#pragma unroll
        for (int i = 0; i < 8; i++) {
            int idx = tid + i * 128;
            int row = idx >> 3, seg = idx & 7;
            CP16(sB + row * APITCH + seg * 16, Bsrc + (size_t)row * KB + seg * 16);
        }
    };

    load_stage(0, 0);
    asm volatile("cp.async.commit_group;" ::: "memory");
    load_stage(1, 1);
    asm volatile("cp.async.commit_group;" ::: "memory");

    const uint32_t aoff = (uint32_t)((wm * 64 + (lane & 15)) * APITCH + (lane >> 4) * 16);
    const uint32_t boff = (uint32_t)((wn * 64 + (lane & 7) + ((lane >> 4) & 1) * 8) * APITCH
                                     + ((lane >> 3) & 1) * 16);

    uint32_t af[2][4][4];
    uint32_t bf[2][8][2];

    auto ldsm_ks = [&](uint32_t sA, uint32_t sB, int ks, int buf) {
        const uint32_t kbyte = (uint32_t)ks * 32;
#pragma unroll
        for (int mi = 0; mi < 4; mi++)
            LDSM4(af[buf][mi][0], af[buf][mi][1], af[buf][mi][2], af[buf][mi][3],
                  sA + aoff + mi * (16 * APITCH) + kbyte);
#pragma unroll
        for (int nt = 0; nt < 4; nt++) {
            uint32_t r0, r1, r2, r3;
            LDSM4(r0, r1, r2, r3, sB + boff + nt * (16 * APITCH) + kbyte);
            bf[buf][2 * nt][0] = r0;     bf[buf][2 * nt][1] = r1;
            bf[buf][2 * nt + 1][0] = r2; bf[buf][2 * nt + 1][1] = r3;
        }
    };

    for (int kt = 0; kt < NK2; kt++) {
        const int s = kt % 3;
        asm volatile("cp.async.wait_group 1;" ::: "memory");
        __syncthreads();
        if (kt + 2 < NK2) load_stage((kt + 2) % 3, kt + 2);
        asm volatile("cp.async.commit_group;" ::: "memory");

        const uint32_t sA = sb + s * GSTAGE;
        const uint32_t sB = sA + ASTAGE;
        ldsm_ks(sA, sB, 0, 0);
#pragma unroll
        for (int ks = 0; ks < 4; ks++) {
            const int cur = ks & 1;
            if (ks < 3) ldsm_ks(sA, sB, ks + 1, cur ^ 1);
#pragma unroll
            for (int mi = 0; mi < 4; mi++)
#pragma unroll
                for (int nj = 0; nj < 8; nj++)
                    MMA16816(acc[mi][nj], af[cur][mi], bf[cur][nj]);
        }
    }
    asm volatile("cp.async.wait_group 0;" ::: "memory");

#pragma unroll
    for (int mi = 0; mi < 4; mi++) {
#pragma unroll
        for (int nj = 0; nj < 8; nj++) {
            int row = mb + wm * 64 + mi * 16 + (lane >> 2);
            int col = nb + wn * 64 + nj * 8 + (lane & 3) * 2;
            float* p0 = d_S + (size_t)row * N_TOT + col;
            float* p1 = d_S + (size_t)(row + 8) * N_TOT + col;
            *(float2*)p0 = make_float2(acc[mi][nj][0], acc[mi][nj][1]);
            *(float2*)p1 = make_float2(acc[mi][nj][2], acc[mi][nj][3]);
        }
    }
}

// ---------------------------------------------------------------------------
// gram3: G = X X^T per item, float4-vectorized inner loop.
// ---------------------------------------------------------------------------
__global__ __launch_bounds__(256)
void gram2_kernel(const float* __restrict__ imgs, const float* __restrict__ caps) {
    const int item = blockIdx.x;
    const bool isCap = item >= N_IMG;
    const float* X = isCap ? caps + (size_t)(item - N_IMG) * N_WORD * DIM
                           : imgs + (size_t)item * N_REG * DIM;
    const int R = isCap ? N_WORD : N_REG;

    __shared__ __align__(16) float xs[36][260];
    const int tid = threadIdx.x;
    const int tr = (tid % 12) * 3;
    const int tc = (tid / 12) * 2;
    const bool act = tid < 216;

    float acc00 = 0.f, acc01 = 0.f, acc10 = 0.f, acc11 = 0.f, acc20 = 0.f, acc21 = 0.f;

    for (int k0 = 0; k0 < DIM; k0 += 256) {
        __syncthreads();
        for (int idx = tid; idx < 36 * 64; idx += 256) {
            int r = idx >> 6, kq = idx & 63;
            float4 v = (r < R) ? ((const float4*)(X + (size_t)r * DIM + k0))[kq]
                               : make_float4(0.f, 0.f, 0.f, 0.f);
            *(float4*)&xs[r][kq * 4] = v;
        }
        __syncthreads();
        if (act) {
            const float4* A0 = (const float4*)xs[tr];
            const float4* A1 = (const float4*)xs[tr + 1];
            const float4* A2 = (const float4*)xs[tr + 2];
            const float4* B0 = (const float4*)xs[tc];
            const float4* B1 = (const float4*)xs[tc + 1];
#pragma unroll 8
            for (int kq = 0; kq < 64; kq++) {
                float4 a0 = A0[kq], a1 = A1[kq], a2 = A2[kq];
                float4 b0 = B0[kq], b1 = B1[kq];
                acc00 += a0.x * b0.x + a0.y * b0.y + a0.z * b0.z + a0.w * b0.w;
                acc01 += a0.x * b1.x + a0.y * b1.y + a0.z * b1.z + a0.w * b1.w;
                acc10 += a1.x * b0.x + a1.y * b0.y + a1.z * b0.z + a1.w * b0.w;
                acc11 += a1.x * b1.x + a1.y * b1.y + a1.z * b1.z + a1.w * b1.w;
                acc20 += a2.x * b0.x + a2.y * b0.y + a2.z * b0.z + a2.w * b0.w;
                acc21 += a2.x * b1.x + a2.y * b1.y + a2.z * b1.z + a2.w * b1.w;
            }
        }
    }
    if (act) {
        float* G = isCap ? d_Gc + (size_t)(item - N_IMG) * (N_WORD * N_WORD)
                         : d_Gi + (size_t)item * (N_REG * N_REG);
        float v[3][2] = {{acc00, acc01}, {acc10, acc11}, {acc20, acc21}};
#pragma unroll
        for (int i = 0; i < 3; i++)
#pragma unroll
            for (int j = 0; j < 2; j++) {
                int r = tr + i, c2 = tc + j;
                if (r < R && c2 < R) G[r * R + c2] = v[i][j];
            }
    }
}

// ---------------------------------------------------------------------------
// attention v9: one CTA per (image, caption-PAIR), 96 threads (3 warps).
// Same v7 per-pair structure (validated), but 2 captions per CTA:
// Gi fill, barriers, launch overhead amortized. No syncs inside pair loop.
// ---------------------------------------------------------------------------
__global__ __launch_bounds__(96, 6)
void attn_kernel(float* __restrict__ out) {
    const int i = blockIdx.x, c0 = blockIdx.y * 2, tid = threadIdx.x;

    __shared__ __align__(16) float Ss[2][36][36];
    __shared__ __align__(16) float Gi[36][40];
    __shared__ __align__(16) float Gc[2][32][32];
    __shared__ float irn_t[2][36], irn_i[2][32];
    __shared__ float red[2][3];

    // --- vectorized fills (both captions) ---
    const size_t srow4 = N_TOT / 4;
#pragma unroll
    for (int p = 0; p < 2; p++) {
        const float4* Sblk4 = (const float4*)(d_S + (size_t)(i * N_REG) * N_TOT + (c0 + p) * N_WORD);
        for (int idx = tid; idx < 36 * 8; idx += 96) {
            int r = idx >> 3, q = idx & 7;
            *(float4*)&Ss[p][r][q * 4] = Sblk4[(size_t)r * srow4 + q];
        }
        const float4* gc4 = (const float4*)(d_Gc + (size_t)(c0 + p) * (32 * 32));
        for (int idx = tid; idx < 256; idx += 96) {
            ((float4*)Gc[p])[idx] = gc4[idx];
        }
    }
    const float4* gi4 = (const float4*)(d_Gi + (size_t)i * (36 * 36));
    for (int idx = tid; idx < 324; idx += 96) {
        int e = idx * 4, r = e / 36, col = e - r * 36;
        *(float4*)&Gi[r][col] = gi4[idx];
    }
    __syncthreads();

    // --- norms of lrelu(S): rows (t2i) and cols (i2t), both captions ---
    if (tid < 36) {
#pragma unroll
        for (int p = 0; p < 2; p++) {
            float s0 = 0.f, s1 = 0.f;
#pragma unroll
            for (int w = 0; w < 32; w += 2) {
                float v0 = lrelu(Ss[p][tid][w]);     s0 += v0 * v0;
                float v1 = lrelu(Ss[p][tid][w + 1]); s1 += v1 * v1;
            }
            irn_t[p][tid] = __fdividef(1.f, sqrtf(s0 + s1) + EPSV);
        }
    } else if (tid < 68) {
        int w = tid - 36;
#pragma unroll
        for (int p = 0; p < 2; p++) {
            float s0 = 0.f, s1 = 0.f;
#pragma unroll
            for (int r = 0; r < 36; r += 2) {
                float v0 = lrelu(Ss[p][r][w]);     s0 += v0 * v0;
                float v1 = lrelu(Ss[p][r + 1][w]); s1 += v1 * v1;
            }
            irn_i[p][w] = __fdividef(1.f, sqrtf(s0 + s1) + EPSV);
        }
    }
    __syncthreads();

    const int wid = tid >> 5, lane = tid & 31;

#pragma unroll 1
    for (int p = 0; p < 2; p++) {
        float val = 0.f;

        if (wid == 0) {
            // ---- t2i: query = word (lane), context = 36 regions ----
            const int w = lane;
            float a[36];
            float mx = -1e30f;
#pragma unroll
            for (int r = 0; r < 36; r++) {
                float v = lrelu(Ss[p][r][w]) * irn_t[p][r];
                a[r] = v; mx = fmaxf(mx, v);
            }
            float esum = 0.f;
#pragma unroll
            for (int r = 0; r < 36; r++) { float e = __expf(LAMBDA * (a[r] - mx)); a[r] = e; esum += e; }
            float th = esum * (1.f / 36.f), tsum = 0.f;
#pragma unroll
            for (int r = 0; r < 36; r++) { float v = (a[r] > th) ? a[r] : 0.f; a[r] = v; tsum += v; }
            float inv = __fdividef(1.f, tsum), num = 0.f;
#pragma unroll
            for (int r = 0; r < 36; r++) { a[r] *= inv; num += a[r] * Ss[p][r][w]; }
            float den0 = 0.f, den1 = 0.f;
#pragma unroll
            for (int r = 0; r < 36; r += 2) {
                const float4* Gr0 = (const float4*)Gi[r];
                const float4* Gr1 = (const float4*)Gi[r + 1];
                float x0 = 0.f, x1 = 0.f, x2 = 0.f, x3 = 0.f;
                float z0 = 0.f, z1 = 0.f, z2 = 0.f, z3 = 0.f;
#pragma unroll
                for (int q = 0; q < 9; q++) {
                    float4 g0 = Gr0[q], g1 = Gr1[q];
                    x0 += g0.x * a[4 * q + 0]; z0 += g1.x * a[4 * q + 0];
                    x1 += g0.y * a[4 * q + 1]; z1 += g1.y * a[4 * q + 1];
                    x2 += g0.z * a[4 * q + 2]; z2 += g1.z * a[4 * q + 2];
                    x3 += g0.w * a[4 * q + 3]; z3 += g1.w * a[4 * q + 3];
                }
                den0 += a[r] * ((x0 + x1) + (x2 + x3));
                den1 += a[r + 1] * ((z0 + z1) + (z2 + z3));
            }
            float den = den0 + den1;
            val = num * __fdividef(1.f,
                  fmaxf(sqrtf(Gc[p][w][w]), EPSV) * fmaxf(sqrtf(den), EPSV));
        } else {
            // ---- i2t: query = region, context = 32 words ----
            const bool valid = (wid == 1) || (lane < 4);
            const int r = valid ? ((wid == 1) ? lane : 32 + lane) : 35;
            float a[32];
            float mx = -1e30f;
#pragma unroll
            for (int w = 0; w < 32; w++) {
                float v = lrelu(Ss[p][r][w]) * irn_i[p][w];
                a[w] = v; mx = fmaxf(mx, v);
            }
            float esum = 0.f;
#pragma unroll
            for (int w = 0; w < 32; w++) { float e = __expf(LAMBDA * (a[w] - mx)); a[w] = e; esum += e; }
            float th = esum * (1.f / 32.f), tsum = 0.f;
#pragma unroll
            for (int w = 0; w < 32; w++) { float v = (a[w] > th) ? a[w] : 0.f; a[w] = v; tsum += v; }
            float inv = __fdividef(1.f, tsum), num = 0.f;
#pragma unroll
            for (int w = 0; w < 32; w++) { a[w] *= inv; num += a[w] * Ss[p][r][w]; }
            float den0 = 0.f, den1 = 0.f;
#pragma unroll
            for (int w = 0; w < 32; w += 2) {
                const float4* Gr0 = (const float4*)Gc[p][w];
                const float4* Gr1 = (const float4*)Gc[p][w + 1];
                float x0 = 0.f, x1 = 0.f, x2 = 0.f, x3 = 0.f;
                float z0 = 0.f, z1 = 0.f, z2 = 0.f, z3 = 0.f;
#pragma unroll
                for (int q = 0; q < 8; q++) {
                    float4 g0 = Gr0[q], g1 = Gr1[q];
                    x0 += g0.x * a[4 * q + 0]; z0 += g1.x * a[4 * q + 0];
                    x1 += g0.y * a[4 * q + 1]; z1 += g1.y * a[4 * q + 1];
                    x2 += g0.z * a[4 * q + 2]; z2 += g1.z * a[4 * q + 2];
                    x3 += g0.w * a[4 * q + 3]; z3 += g1.w * a[4 * q + 3];
                }
                den0 += a[w] * ((x0 + x1) + (x2 + x3));
                den1 += a[w + 1] * ((z0 + z1) + (z2 + z3));
            }
            float den = den0 + den1;
            float v = num * __fdividef(1.f,
                      fmaxf(sqrtf(Gi[r][r]), EPSV) * fmaxf(sqrtf(den), EPSV));
            val = valid ? v : 0.f;
        }

        // warp-level sum
#pragma unroll
        for (int off = 16; off > 0; off >>= 1)
            val += __shfl_xor_sync(0xFFFFFFFFu, val, off);
        if (lane == 0) red[p][wid] = val;
    }
    __syncthreads();
    if (tid < 2)
        out[i * N_CAP + c0 + tid] =
            red[tid][0] * (1.f / 32.f) + (red[tid][1] + red[tid][2]) * (1.f / 36.f);
}

// ---------------------------------------------------------------------------
extern "C" void kernel_launch(void* const* d_in, const int* in_sizes, int n_in,
                              void* d_out, int out_size) {
    const float* images   = (const float*)d_in[0];   // (128,36,1024)
    const float* captions = (const float*)d_in[1];   // (128,32,1024)
    float* out = (float*)d_out;                       // (128,128)

    prep_kernel<<<(M_TOT * DIM / 2) / 256, 256>>>(images, M_TOT * DIM / 2, 0);
    prep_kernel<<<(N_TOT * DIM / 2) / 256, 256>>>(captions, N_TOT * DIM / 2, 1);
    gram2_kernel<<<256, 256>>>(images, captions);

    cudaFuncSetAttribute(gemm_kernel, cudaFuncAttributeMaxDynamicSharedMemorySize, GEMM_SMEM);
    dim3 ggrid(N_TOT / 128, M_TOT / 128);   // (32, 36)
    gemm_kernel<<<ggrid, 128, GEMM_SMEM>>>();

    dim3 agrid(N_IMG, N_CAP / 2);            // (128, 64)
    attn_kernel<<<agrid, 96>>>(out);
}

// round 15
// speedup vs baseline: 1.1404x; 1.0652x over previous
#include <cuda_runtime.h>
#include <cuda_bf16.h>
#include <math.h>
#include <stdint.h>

#define N_IMG  128
#define N_REG  36
#define N_CAP  128
#define N_WORD 32
#define DIM    1024
#define LAMBDA 20.0f
#define EPSV   1e-8f
#define SLOPE  0.1f

#define M_TOT 4608              // 128*36
#define N_TOT 4096              // 128*32
#define KCAT  3072              // 3 * 1024 (hi/lo concat)
#define KB    (KCAT * 2)        // 6144 bytes per row
#define NK2   48                // KCAT / 64

// ---------------- scratch (static; no cudaMalloc allowed) ----------------
__device__ __align__(256) float         d_S[(size_t)M_TOT * N_TOT];     // 75.5MB
__device__ __align__(256) __nv_bfloat16 d_Acat[(size_t)M_TOT * KCAT];   // [Ah|Ah|Al]
__device__ __align__(256) __nv_bfloat16 d_Bcat[(size_t)N_TOT * KCAT];   // [Bh|Bl|Bh]
__device__ __align__(256) float d_Gi[N_IMG * N_REG * N_REG];
__device__ __align__(256) float d_Gc[N_CAP * N_WORD * N_WORD];

__device__ __forceinline__ float lrelu(float x) { return x > 0.f ? x : SLOPE * x; }

__device__ __forceinline__ uint32_t smem_u32(const void* p) {
    uint32_t a;
    asm("{ .reg .u64 t; cvta.to.shared.u64 t, %1; cvt.u32.u64 %0, t; }" : "=r"(a) : "l"(p));
    return a;
}

// packed f32x2 fused multiply-add: d = a*b + d (elementwise on 2 lanes)
__device__ __forceinline__ void ffma2(uint64_t& d, uint64_t a, uint64_t b) {
    asm("fma.rn.f32x2 %0, %1, %2, %0;" : "+l"(d) : "l"(a), "l"(b));
}
__device__ __forceinline__ float f2sum(uint64_t v) {
    float lo, hi;
    asm("mov.b64 {%0, %1}, %2;" : "=f"(lo), "=f"(hi) : "l"(v));
    return lo + hi;
}
__device__ __forceinline__ uint64_t f2pack(float lo, float hi) {
    uint64_t v;
    asm("mov.b64 %0, {%1, %2};" : "=l"(v) : "f"(lo), "f"(hi));
    return v;
}

#define LDSM4(r0, r1, r2, r3, addr) \
    asm volatile("ldmatrix.sync.aligned.m8n8.x4.shared.b16 {%0,%1,%2,%3}, [%4];" \
        : "=r"(r0), "=r"(r1), "=r"(r2), "=r"(r3) : "r"(addr))

#define MMA16816(d, a, b) \
    asm volatile("mma.sync.aligned.m16n8k16.row.col.f32.bf16.bf16.f32 " \
        "{%0,%1,%2,%3}, {%4,%5,%6,%7}, {%8,%9}, {%0,%1,%2,%3};" \
        : "+f"((d)[0]), "+f"((d)[1]), "+f"((d)[2]), "+f"((d)[3]) \
        : "r"((a)[0]), "r"((a)[1]), "r"((a)[2]), "r"((a)[3]), "r"((b)[0]), "r"((b)[1]))

#define CP16(dst, src) \
    asm volatile("cp.async.cg.shared.global [%0], [%1], 16;" :: "r"(dst), "l"(src))

// ---------------------------------------------------------------------------
// prep (vectorized): fp32 -> bf16 hi/lo concat, 2 elements per thread.
// ---------------------------------------------------------------------------
__global__ void prep_kernel(const float* __restrict__ X, int totalPairs, int sel) {
    int p = blockIdx.x * blockDim.x + threadIdx.x;
    if (p >= totalPairs) return;
    float2 v = *(const float2*)(X + 2 * (size_t)p);
    __nv_bfloat16 h0 = __float2bfloat16(v.x);
    __nv_bfloat16 h1 = __float2bfloat16(v.y);
    __nv_bfloat16 l0 = __float2bfloat16(v.x - __bfloat162float(h0));
    __nv_bfloat16 l1 = __float2bfloat16(v.y - __bfloat162float(h1));
    uint32_t hh = ((uint32_t)*(uint16_t*)&h1 << 16) | *(uint16_t*)&h0;
    uint32_t ll = ((uint32_t)*(uint16_t*)&l1 << 16) | *(uint16_t*)&l0;
    int row = p >> 9, kp = p & 511;
    uint32_t* out = (uint32_t*)(sel ? d_Bcat : d_Acat);
    size_t base = (size_t)row * (KCAT / 2) + kp;
    out[base] = hh;
    out[base + 512]  = sel ? ll : hh;
    out[base + 1024] = sel ? hh : ll;
}

// ---------------------------------------------------------------------------
// bf16 mma.sync GEMM (round-10 config): S = Acat @ Bcat^T, fp32 accum.
// CTA 128x128, BK=64, 3-stage cp.async, 4 warps (2m x 2n), warp tile 64x64,
// 2 CTAs/SM, fragment double-buffering across ks steps.
// ---------------------------------------------------------------------------
#define APITCH 144
#define ASTAGE (128 * APITCH)          // 18432
#define GSTAGE (2 * ASTAGE)            // 36864
#define GEMM_SMEM (3 * GSTAGE)         // 110592

__global__ __launch_bounds__(128, 2)
void gemm_kernel() {
    extern __shared__ char smem[];
    const uint32_t sb = smem_u32(smem);
    const int tid  = threadIdx.x;
    const int lane = tid & 31;
    const int wid  = tid >> 5;
    const int wm   = wid & 1;
    const int wn   = wid >> 1;
    const int mb   = blockIdx.y * 128;
    const int nb   = blockIdx.x * 128;

    const char* Ag = (const char*)d_Acat + (size_t)mb * KB;
    const char* Bg = (const char*)d_Bcat + (size_t)nb * KB;

    float acc[4][8][4];
#pragma unroll
    for (int i = 0; i < 4; i++)
#pragma unroll
        for (int j = 0; j < 8; j++)
#pragma unroll
            for (int q = 0; q < 4; q++) acc[i][j][q] = 0.f;

    auto load_stage = [&](int s, int kt) {
        const uint32_t sA = sb + s * GSTAGE;
        const uint32_t sB = sA + ASTAGE;
        const char* Asrc = Ag + kt * 128;
        const char* Bsrc = Bg + kt * 128;
#pragma unroll
        for (int i = 0; i < 8; i++) {
            int idx = tid + i * 128;
            int row = idx >> 3, seg = idx & 7;
            CP16(sA + row * APITCH + seg * 16, Asrc + (size_t)row * KB + seg * 16);
        }
#pragma unroll
        for (int i = 0; i < 8; i++) {
            int idx = tid + i * 128;
            int row = idx >> 3, seg = idx & 7;
            CP16(sB + row * APITCH + seg * 16, Bsrc + (size_t)row * KB + seg * 16);
        }
    };

    load_stage(0, 0);
    asm volatile("cp.async.commit_group;" ::: "memory");
    load_stage(1, 1);
    asm volatile("cp.async.commit_group;" ::: "memory");

    const uint32_t aoff = (uint32_t)((wm * 64 + (lane & 15)) * APITCH + (lane >> 4) * 16);
    const uint32_t boff = (uint32_t)((wn * 64 + (lane & 7) + ((lane >> 4) & 1) * 8) * APITCH
                                     + ((lane >> 3) & 1) * 16);

    uint32_t af[2][4][4];
    uint32_t bf[2][8][2];

    auto ldsm_ks = [&](uint32_t sA, uint32_t sB, int ks, int buf) {
        const uint32_t kbyte = (uint32_t)ks * 32;
#pragma unroll
        for (int mi = 0; mi < 4; mi++)
            LDSM4(af[buf][mi][0], af[buf][mi][1], af[buf][mi][2], af[buf][mi][3],
                  sA + aoff + mi * (16 * APITCH) + kbyte);
#pragma unroll
        for (int nt = 0; nt < 4; nt++) {
            uint32_t r0, r1, r2, r3;
            LDSM4(r0, r1, r2, r3, sB + boff + nt * (16 * APITCH) + kbyte);
            bf[buf][2 * nt][0] = r0;     bf[buf][2 * nt][1] = r1;
            bf[buf][2 * nt + 1][0] = r2; bf[buf][2 * nt + 1][1] = r3;
        }
    };

    for (int kt = 0; kt < NK2; kt++) {
        const int s = kt % 3;
        asm volatile("cp.async.wait_group 1;" ::: "memory");
        __syncthreads();
        if (kt + 2 < NK2) load_stage((kt + 2) % 3, kt + 2);
        asm volatile("cp.async.commit_group;" ::: "memory");

        const uint32_t sA = sb + s * GSTAGE;
        const uint32_t sB = sA + ASTAGE;
        ldsm_ks(sA, sB, 0, 0);
#pragma unroll
        for (int ks = 0; ks < 4; ks++) {
            const int cur = ks & 1;
            if (ks < 3) ldsm_ks(sA, sB, ks + 1, cur ^ 1);
#pragma unroll
            for (int mi = 0; mi < 4; mi++)
#pragma unroll
                for (int nj = 0; nj < 8; nj++)
                    MMA16816(acc[mi][nj], af[cur][mi], bf[cur][nj]);
        }
    }
    asm volatile("cp.async.wait_group 0;" ::: "memory");

#pragma unroll
    for (int mi = 0; mi < 4; mi++) {
#pragma unroll
        for (int nj = 0; nj < 8; nj++) {
            int row = mb + wm * 64 + mi * 16 + (lane >> 2);
            int col = nb + wn * 64 + nj * 8 + (lane & 3) * 2;
            float* p0 = d_S + (size_t)row * N_TOT + col;
            float* p1 = d_S + (size_t)(row + 8) * N_TOT + col;
            *(float2*)p0 = make_float2(acc[mi][nj][0], acc[mi][nj][1]);
            *(float2*)p1 = make_float2(acc[mi][nj][2], acc[mi][nj][3]);
        }
    }
}

// ---------------------------------------------------------------------------
// gram3: G = X X^T per item, float4-vectorized inner loop.
// ---------------------------------------------------------------------------
__global__ __launch_bounds__(256)
void gram2_kernel(const float* __restrict__ imgs, const float* __restrict__ caps) {
    const int item = blockIdx.x;
    const bool isCap = item >= N_IMG;
    const float* X = isCap ? caps + (size_t)(item - N_IMG) * N_WORD * DIM
                           : imgs + (size_t)item * N_REG * DIM;
    const int R = isCap ? N_WORD : N_REG;

    __shared__ __align__(16) float xs[36][260];
    const int tid = threadIdx.x;
    const int tr = (tid % 12) * 3;
    const int tc = (tid / 12) * 2;
    const bool act = tid < 216;

    float acc00 = 0.f, acc01 = 0.f, acc10 = 0.f, acc11 = 0.f, acc20 = 0.f, acc21 = 0.f;

    for (int k0 = 0; k0 < DIM; k0 += 256) {
        __syncthreads();
        for (int idx = tid; idx < 36 * 64; idx += 256) {
            int r = idx >> 6, kq = idx & 63;
            float4 v = (r < R) ? ((const float4*)(X + (size_t)r * DIM + k0))[kq]
                               : make_float4(0.f, 0.f, 0.f, 0.f);
            *(float4*)&xs[r][kq * 4] = v;
        }
        __syncthreads();
        if (act) {
            const float4* A0 = (const float4*)xs[tr];
            const float4* A1 = (const float4*)xs[tr + 1];
            const float4* A2 = (const float4*)xs[tr + 2];
            const float4* B0 = (const float4*)xs[tc];
            const float4* B1 = (const float4*)xs[tc + 1];
#pragma unroll 8
            for (int kq = 0; kq < 64; kq++) {
                float4 a0 = A0[kq], a1 = A1[kq], a2 = A2[kq];
                float4 b0 = B0[kq], b1 = B1[kq];
                acc00 += a0.x * b0.x + a0.y * b0.y + a0.z * b0.z + a0.w * b0.w;
                acc01 += a0.x * b1.x + a0.y * b1.y + a0.z * b1.z + a0.w * b1.w;
                acc10 += a1.x * b0.x + a1.y * b0.y + a1.z * b0.z + a1.w * b0.w;
                acc11 += a1.x * b1.x + a1.y * b1.y + a1.z * b1.z + a1.w * b1.w;
                acc20 += a2.x * b0.x + a2.y * b0.y + a2.z * b0.z + a2.w * b0.w;
                acc21 += a2.x * b1.x + a2.y * b1.y + a2.z * b1.z + a2.w * b1.w;
            }
        }
    }
    if (act) {
        float* G = isCap ? d_Gc + (size_t)(item - N_IMG) * (N_WORD * N_WORD)
                         : d_Gi + (size_t)item * (N_REG * N_REG);
        float v[3][2] = {{acc00, acc01}, {acc10, acc11}, {acc20, acc21}};
#pragma unroll
        for (int i = 0; i < 3; i++)
#pragma unroll
            for (int j = 0; j < 2; j++) {
                int r = tr + i, c2 = tc + j;
                if (r < R && c2 < R) G[r * R + c2] = v[i][j];
            }
    }
}

// ---------------------------------------------------------------------------
// attention v10: round-12 v7 structure + packed fma.rn.f32x2 quadratic forms.
// One CTA per (image, caption), 96 threads (3 warps), occupancy 6.
// ---------------------------------------------------------------------------
__global__ __launch_bounds__(96, 6)
void attn_kernel(float* __restrict__ out) {
    const int i = blockIdx.x, c = blockIdx.y, tid = threadIdx.x;

    __shared__ __align__(16) float Ss[36][36];
    __shared__ __align__(16) float Gi[36][40];
    __shared__ __align__(16) float Gc[32][32];
    __shared__ float irn_t[36], irn_i[32];
    __shared__ float red[3];

    const float4* Sblk4 = (const float4*)(d_S + (size_t)(i * N_REG) * N_TOT + c * N_WORD);
    const size_t srow4 = N_TOT / 4;
    for (int idx = tid; idx < 36 * 8; idx += 96) {
        int r = idx >> 3, q = idx & 7;
        *(float4*)&Ss[r][q * 4] = Sblk4[(size_t)r * srow4 + q];
    }
    const float4* gi4 = (const float4*)(d_Gi + (size_t)i * (36 * 36));
    for (int idx = tid; idx < 324; idx += 96) {
        int e = idx * 4, r = e / 36, col = e - r * 36;
        *(float4*)&Gi[r][col] = gi4[idx];
    }
    const float4* gc4 = (const float4*)(d_Gc + (size_t)c * (32 * 32));
    for (int idx = tid; idx < 256; idx += 96) {
        ((float4*)Gc)[idx] = gc4[idx];
    }
    __syncthreads();

    if (tid < 36) {
        float s0 = 0.f, s1 = 0.f;
#pragma unroll
        for (int w = 0; w < 32; w += 2) {
            float v0 = lrelu(Ss[tid][w]);     s0 += v0 * v0;
            float v1 = lrelu(Ss[tid][w + 1]); s1 += v1 * v1;
        }
        irn_t[tid] = __fdividef(1.f, sqrtf(s0 + s1) + EPSV);
    } else if (tid < 68) {
        int w = tid - 36;
        float s0 = 0.f, s1 = 0.f;
#pragma unroll
        for (int r = 0; r < 36; r += 2) {
            float v0 = lrelu(Ss[r][w]);     s0 += v0 * v0;
            float v1 = lrelu(Ss[r + 1][w]); s1 += v1 * v1;
        }
        irn_i[w] = __fdividef(1.f, sqrtf(s0 + s1) + EPSV);
    }
    __syncthreads();

    const int wid = tid >> 5, lane = tid & 31;
    float val = 0.f;

    if (wid == 0) {
        // ---- t2i: query = word (lane), context = 36 regions ----
        const int w = lane;
        float a[36];
        float mx = -1e30f;
#pragma unroll
        for (int r = 0; r < 36; r++) {
            float v = lrelu(Ss[r][w]) * irn_t[r];
            a[r] = v; mx = fmaxf(mx, v);
        }
        float esum = 0.f;
#pragma unroll
        for (int r = 0; r < 36; r++) { float e = __expf(LAMBDA * (a[r] - mx)); a[r] = e; esum += e; }
        float th = esum * (1.f / 36.f), tsum = 0.f;
#pragma unroll
        for (int r = 0; r < 36; r++) { float v = (a[r] > th) ? a[r] : 0.f; a[r] = v; tsum += v; }
        float inv = __fdividef(1.f, tsum), num = 0.f;
#pragma unroll
        for (int r = 0; r < 36; r++) { a[r] *= inv; num += a[r] * Ss[r][w]; }
        // pack a[] into f32x2 pairs
        uint64_t a2[18];
#pragma unroll
        for (int q = 0; q < 18; q++) a2[q] = f2pack(a[2 * q], a[2 * q + 1]);
        // quadratic form: a^T Gi a via LDS.128 rows + packed FFMA2, 2-row split
        float den0 = 0.f, den1 = 0.f;
#pragma unroll
        for (int r = 0; r < 36; r += 2) {
            const ulonglong2* Gr0 = (const ulonglong2*)Gi[r];
            const ulonglong2* Gr1 = (const ulonglong2*)Gi[r + 1];
            uint64_t xa = 0, xb = 0, za = 0, zb = 0;
#pragma unroll
            for (int q = 0; q < 9; q++) {
                ulonglong2 g0 = Gr0[q], g1 = Gr1[q];
                ffma2(xa, g0.x, a2[2 * q]);
                ffma2(xb, g0.y, a2[2 * q + 1]);
                ffma2(za, g1.x, a2[2 * q]);
                ffma2(zb, g1.y, a2[2 * q + 1]);
            }
            den0 += a[r] * (f2sum(xa) + f2sum(xb));
            den1 += a[r + 1] * (f2sum(za) + f2sum(zb));
        }
        float den = den0 + den1;
        val = num * __fdividef(1.f,
              fmaxf(sqrtf(Gc[w][w]), EPSV) * fmaxf(sqrtf(den), EPSV));
    } else {
        // ---- i2t: query = region, context = 32 words ----
        const bool valid = (wid == 1) || (lane < 4);
        const int r = valid ? ((wid == 1) ? lane : 32 + lane) : 35;
        float a[32];
        float mx = -1e30f;
#pragma unroll
        for (int w = 0; w < 32; w++) {
            float v = lrelu(Ss[r][w]) * irn_i[w];
            a[w] = v; mx = fmaxf(mx, v);
        }
        float esum = 0.f;
#pragma unroll
        for (int w = 0; w < 32; w++) { float e = __expf(LAMBDA * (a[w] - mx)); a[w] = e; esum += e; }
        float th = esum * (1.f / 32.f), tsum = 0.f;
#pragma unroll
        for (int w = 0; w < 32; w++) { float v = (a[w] > th) ? a[w] : 0.f; a[w] = v; tsum += v; }
        float inv = __fdividef(1.f, tsum), num = 0.f;
#pragma unroll
        for (int w = 0; w < 32; w++) { a[w] *= inv; num += a[w] * Ss[r][w]; }
        uint64_t a2[16];
#pragma unroll
        for (int q = 0; q < 16; q++) a2[q] = f2pack(a[2 * q], a[2 * q + 1]);
        float den0 = 0.f, den1 = 0.f;
#pragma unroll
        for (int w = 0; w < 32; w += 2) {
            const ulonglong2* Gr0 = (const ulonglong2*)Gc[w];
            const ulonglong2* Gr1 = (const ulonglong2*)Gc[w + 1];
            uint64_t xa = 0, xb = 0, za = 0, zb = 0;
#pragma unroll
            for (int q = 0; q < 8; q++) {
                ulonglong2 g0 = Gr0[q], g1 = Gr1[q];
                ffma2(xa, g0.x, a2[2 * q]);
                ffma2(xb, g0.y, a2[2 * q + 1]);
                ffma2(za, g1.x, a2[2 * q]);
                ffma2(zb, g1.y, a2[2 * q + 1]);
            }
            den0 += a[w] * (f2sum(xa) + f2sum(xb));
            den1 += a[w + 1] * (f2sum(za) + f2sum(zb));
        }
        float den = den0 + den1;
        float v = num * __fdividef(1.f,
                  fmaxf(sqrtf(Gi[r][r]), EPSV) * fmaxf(sqrtf(den), EPSV));
        val = valid ? v : 0.f;
    }

#pragma unroll
    for (int off = 16; off > 0; off >>= 1)
        val += __shfl_xor_sync(0xFFFFFFFFu, val, off);
    if (lane == 0) red[wid] = val;
    __syncthreads();
    if (tid == 0)
        out[i * N_CAP + c] = red[0] * (1.f / 32.f) + (red[1] + red[2]) * (1.f / 36.f);
}

// ---------------------------------------------------------------------------
extern "C" void kernel_launch(void* const* d_in, const int* in_sizes, int n_in,
                              void* d_out, int out_size) {
    const float* images   = (const float*)d_in[0];   // (128,36,1024)
    const float* captions = (const float*)d_in[1];   // (128,32,1024)
    float* out = (float*)d_out;                       // (128,128)

    prep_kernel<<<(M_TOT * DIM / 2) / 256, 256>>>(images, M_TOT * DIM / 2, 0);
    prep_kernel<<<(N_TOT * DIM / 2) / 256, 256>>>(captions, N_TOT * DIM / 2, 1);
    gram2_kernel<<<256, 256>>>(images, captions);

    cudaFuncSetAttribute(gemm_kernel, cudaFuncAttributeMaxDynamicSharedMemorySize, GEMM_SMEM);
    dim3 ggrid(N_TOT / 128, M_TOT / 128);   // (32, 36)
    gemm_kernel<<<ggrid, 128, GEMM_SMEM>>>();

    dim3 agrid(N_IMG, N_CAP);
    attn_kernel<<<agrid, 96>>>(out);
}

// round 16
// speedup vs baseline: 1.2103x; 1.0612x over previous
#include <cuda_runtime.h>
#include <cuda_bf16.h>
#include <math.h>
#include <stdint.h>

#define N_IMG  128
#define N_REG  36
#define N_CAP  128
#define N_WORD 32
#define DIM    1024
#define LAMBDA 20.0f
#define EPSV   1e-8f
#define SLOPE  0.1f

#define M_TOT 4608              // 128*36
#define N_TOT 4096              // 128*32
#define KCAT  3072              // 3 * 1024 (hi/lo concat)
#define KB    (KCAT * 2)        // 6144 bytes per row
#define NK2   48                // KCAT / 64

// ---------------- scratch (static; no cudaMalloc allowed) ----------------
__device__ __align__(256) __nv_bfloat16 d_Acat[(size_t)M_TOT * KCAT];   // [Ah|Ah|Al]
__device__ __align__(256) __nv_bfloat16 d_Bcat[(size_t)N_TOT * KCAT];   // [Bh|Bl|Bh]
__device__ __align__(256) float d_Gi[N_IMG * N_REG * N_REG];
__device__ __align__(256) float d_Gc[N_CAP * N_WORD * N_WORD];

__device__ __forceinline__ float lrelu(float x) { return x > 0.f ? x : SLOPE * x; }

__device__ __forceinline__ uint32_t smem_u32(const void* p) {
    uint32_t a;
    asm("{ .reg .u64 t; cvta.to.shared.u64 t, %1; cvt.u32.u64 %0, t; }" : "=r"(a) : "l"(p));
    return a;
}

// packed f32x2 fused multiply-add
__device__ __forceinline__ void ffma2(uint64_t& d, uint64_t a, uint64_t b) {
    asm("fma.rn.f32x2 %0, %1, %2, %0;" : "+l"(d) : "l"(a), "l"(b));
}
__device__ __forceinline__ float f2sum(uint64_t v) {
    float lo, hi;
    asm("mov.b64 {%0, %1}, %2;" : "=f"(lo), "=f"(hi) : "l"(v));
    return lo + hi;
}
__device__ __forceinline__ uint64_t f2pack(float lo, float hi) {
    uint64_t v;
    asm("mov.b64 %0, {%1, %2};" : "=l"(v) : "f"(lo), "f"(hi));
    return v;
}

#define LDSM4(r0, r1, r2, r3, addr) \
    asm volatile("ldmatrix.sync.aligned.m8n8.x4.shared.b16 {%0,%1,%2,%3}, [%4];" \
        : "=r"(r0), "=r"(r1), "=r"(r2), "=r"(r3) : "r"(addr))

#define MMA16816(d, a, b) \
    asm volatile("mma.sync.aligned.m16n8k16.row.col.f32.bf16.bf16.f32 " \
        "{%0,%1,%2,%3}, {%4,%5,%6,%7}, {%8,%9}, {%0,%1,%2,%3};" \
        : "+f"((d)[0]), "+f"((d)[1]), "+f"((d)[2]), "+f"((d)[3]) \
        : "r"((a)[0]), "r"((a)[1]), "r"((a)[2]), "r"((a)[3]), "r"((b)[0]), "r"((b)[1]))

#define CP16(dst, src) \
    asm volatile("cp.async.cg.shared.global [%0], [%1], 16;" :: "r"(dst), "l"(src))

// ---------------------------------------------------------------------------
// prep: fp32 -> bf16 hi/lo concat, 2 elements per thread.
// ---------------------------------------------------------------------------
__global__ void prep_kernel(const float* __restrict__ X, int totalPairs, int sel) {
    int p = blockIdx.x * blockDim.x + threadIdx.x;
    if (p >= totalPairs) return;
    float2 v = *(const float2*)(X + 2 * (size_t)p);
    __nv_bfloat16 h0 = __float2bfloat16(v.x);
    __nv_bfloat16 h1 = __float2bfloat16(v.y);
    __nv_bfloat16 l0 = __float2bfloat16(v.x - __bfloat162float(h0));
    __nv_bfloat16 l1 = __float2bfloat16(v.y - __bfloat162float(h1));
    uint32_t hh = ((uint32_t)*(uint16_t*)&h1 << 16) | *(uint16_t*)&h0;
    uint32_t ll = ((uint32_t)*(uint16_t*)&l1 << 16) | *(uint16_t*)&l0;
    int row = p >> 9, kp = p & 511;
    uint32_t* out = (uint32_t*)(sel ? d_Bcat : d_Acat);
    size_t base = (size_t)row * (KCAT / 2) + kp;
    out[base] = hh;
    out[base + 512]  = sel ? ll : hh;
    out[base + 1024] = sel ? hh : ll;
}

// ---------------------------------------------------------------------------
// gram3: G = X X^T per item, float4-vectorized inner loop.
// ---------------------------------------------------------------------------
__global__ __launch_bounds__(256)
void gram2_kernel(const float* __restrict__ imgs, const float* __restrict__ caps) {
    const int item = blockIdx.x;
    const bool isCap = item >= N_IMG;
    const float* X = isCap ? caps + (size_t)(item - N_IMG) * N_WORD * DIM
                           : imgs + (size_t)item * N_REG * DIM;
    const int R = isCap ? N_WORD : N_REG;

    __shared__ __align__(16) float xs[36][260];
    const int tid = threadIdx.x;
    const int tr = (tid % 12) * 3;
    const int tc = (tid / 12) * 2;
    const bool act = tid < 216;

    float acc00 = 0.f, acc01 = 0.f, acc10 = 0.f, acc11 = 0.f, acc20 = 0.f, acc21 = 0.f;

    for (int k0 = 0; k0 < DIM; k0 += 256) {
        __syncthreads();
        for (int idx = tid; idx < 36 * 64; idx += 256) {
            int r = idx >> 6, kq = idx & 63;
            float4 v = (r < R) ? ((const float4*)(X + (size_t)r * DIM + k0))[kq]
                               : make_float4(0.f, 0.f, 0.f, 0.f);
            *(float4*)&xs[r][kq * 4] = v;
        }
        __syncthreads();
        if (act) {
            const float4* A0 = (const float4*)xs[tr];
            const float4* A1 = (const float4*)xs[tr + 1];
            const float4* A2 = (const float4*)xs[tr + 2];
            const float4* B0 = (const float4*)xs[tc];
            const float4* B1 = (const float4*)xs[tc + 1];
#pragma unroll 8
            for (int kq = 0; kq < 64; kq++) {
                float4 a0 = A0[kq], a1 = A1[kq], a2 = A2[kq];
                float4 b0 = B0[kq], b1 = B1[kq];
                acc00 += a0.x * b0.x + a0.y * b0.y + a0.z * b0.z + a0.w * b0.w;
                acc01 += a0.x * b1.x + a0.y * b1.y + a0.z * b1.z + a0.w * b1.w;
                acc10 += a1.x * b0.x + a1.y * b0.y + a1.z * b0.z + a1.w * b0.w;
                acc11 += a1.x * b1.x + a1.y * b1.y + a1.z * b1.z + a1.w * b1.w;
                acc20 += a2.x * b0.x + a2.y * b0.y + a2.z * b0.z + a2.w * b0.w;
                acc21 += a2.x * b1.x + a2.y * b1.y + a2.z * b1.z + a2.w * b1.w;
            }
        }
    }
    if (act) {
        float* G = isCap ? d_Gc + (size_t)(item - N_IMG) * (N_WORD * N_WORD)
                         : d_Gi + (size_t)item * (N_REG * N_REG);
        float v[3][2] = {{acc00, acc01}, {acc10, acc11}, {acc20, acc21}};
#pragma unroll
        for (int i = 0; i < 3; i++)
#pragma unroll
            for (int j = 0; j < 2; j++) {
                int r = tr + i, c2 = tc + j;
                if (r < R && c2 < R) G[r * R + c2] = v[i][j];
            }
    }
}

// ---------------------------------------------------------------------------
// FUSED kernel: GEMM tile M=144 (4 images) x N=128 (4 captions), K=3072 bf16,
// then in-CTA attention epilogue on the 16 (image,caption) pairs.
// 192 threads (6 warps: 3m x 2n, warp tile 48x64), BK=64, 2-stage cp.async.
// smem: 2 stages (78336B) overlaid by S[144][132] fp32 + misc in epilogue,
// plus Gi[4] (20736B) and Gc[4] (16384B). Total 115456B, 2 CTAs/SM.
// ---------------------------------------------------------------------------
#define FPITCH 144
#define FASTG  (144 * FPITCH)                 // 20736 (A stage)
#define FSTAGE ((144 + 128) * FPITCH)         // 39168
#define OFF_GI (2 * FSTAGE)                   // 78336
#define OFF_GC (OFF_GI + 4 * 1296 * 4)        // 99072
#define FSMEM  (OFF_GC + 4 * 1024 * 4)        // 115456
#define PS     132                             // S pitch (floats)
#define OFF_MISC (144 * PS * 4)                // 76032 (inside stage area)

__global__ __launch_bounds__(192, 2)
void fused_kernel(float* __restrict__ out) {
    extern __shared__ char smem[];
    const uint32_t sb = smem_u32(smem);
    const int tid  = threadIdx.x;
    const int lane = tid & 31;
    const int wid  = tid >> 5;
    const int wm   = wid >> 1;         // 0..2 -> m offset *48
    const int wn   = wid & 1;          // 0..1 -> n offset *64
    const int mb   = blockIdx.y * 144;
    const int nb   = blockIdx.x * 128;

    const char* Ag = (const char*)d_Acat + (size_t)mb * KB;
    const char* Bg = (const char*)d_Bcat + (size_t)nb * KB;

    float acc[3][8][4];
#pragma unroll
    for (int i = 0; i < 3; i++)
#pragma unroll
        for (int j = 0; j < 8; j++)
#pragma unroll
            for (int q = 0; q < 4; q++) acc[i][j][q] = 0.f;

    auto load_stage = [&](int s, int kt) {
        const uint32_t sA = sb + s * FSTAGE;
        const uint32_t sB = sA + FASTG;
        const char* Asrc = Ag + kt * 128;
        const char* Bsrc = Bg + kt * 128;
#pragma unroll
        for (int i = 0; i < 6; i++) {              // A: 144*8 = 1152 = 6*192
            int idx = tid + i * 192;
            int row = idx >> 3, seg = idx & 7;
            CP16(sA + row * FPITCH + seg * 16, Asrc + (size_t)row * KB + seg * 16);
        }
#pragma unroll
        for (int i = 0; i < 6; i++) {              // B: 128*8 = 1024
            int idx = tid + i * 192;
            if (idx < 1024) {
                int row = idx >> 3, seg = idx & 7;
                CP16(sB + row * FPITCH + seg * 16, Bsrc + (size_t)row * KB + seg * 16);
            }
        }
    };

    load_stage(0, 0);
    asm volatile("cp.async.commit_group;" ::: "memory");
    load_stage(1, 1);
    asm volatile("cp.async.commit_group;" ::: "memory");

    const uint32_t aoff = (uint32_t)((wm * 48 + (lane & 15)) * FPITCH + (lane >> 4) * 16);
    const uint32_t boff = (uint32_t)((wn * 64 + (lane & 7) + ((lane >> 4) & 1) * 8) * FPITCH
                                     + ((lane >> 3) & 1) * 16);

    for (int kt = 0; kt < NK2; kt++) {
        if (kt < NK2 - 1) asm volatile("cp.async.wait_group 1;" ::: "memory");
        else              asm volatile("cp.async.wait_group 0;" ::: "memory");
        __syncthreads();
        const uint32_t sA = sb + (kt & 1) * FSTAGE;
        const uint32_t sB = sA + FASTG;
#pragma unroll
        for (int ks = 0; ks < 4; ks++) {
            const uint32_t kbyte = (uint32_t)ks * 32;
            uint32_t af[3][4];
#pragma unroll
            for (int mi = 0; mi < 3; mi++)
                LDSM4(af[mi][0], af[mi][1], af[mi][2], af[mi][3],
                      sA + aoff + mi * (16 * FPITCH) + kbyte);
            uint32_t bfr[8][2];
#pragma unroll
            for (int nt = 0; nt < 4; nt++) {
                uint32_t r0, r1, r2, r3;
                LDSM4(r0, r1, r2, r3, sB + boff + nt * (16 * FPITCH) + kbyte);
                bfr[2 * nt][0] = r0;     bfr[2 * nt][1] = r1;
                bfr[2 * nt + 1][0] = r2; bfr[2 * nt + 1][1] = r3;
            }
#pragma unroll
            for (int mi = 0; mi < 3; mi++)
#pragma unroll
                for (int nj = 0; nj < 8; nj++)
                    MMA16816(acc[mi][nj], af[mi], bfr[nj]);
        }
        __syncthreads();
        if (kt + 2 < NK2) {
            load_stage(kt & 1, kt + 2);
            asm volatile("cp.async.commit_group;" ::: "memory");
        }
    }

    // ---------------- epilogue: attn on 16 pairs ----------------
    float* S = (float*)smem;                         // [144][PS]
#pragma unroll
    for (int mi = 0; mi < 3; mi++) {
#pragma unroll
        for (int nj = 0; nj < 8; nj++) {
            int row = wm * 48 + mi * 16 + (lane >> 2);
            int col = wn * 64 + nj * 8 + (lane & 3) * 2;
            S[row * PS + col]     = acc[mi][nj][0];
            S[row * PS + col + 1] = acc[mi][nj][1];
            S[(row + 8) * PS + col]     = acc[mi][nj][2];
            S[(row + 8) * PS + col + 1] = acc[mi][nj][3];
        }
    }
    // load Gram matrices (4 images, 4 captions)
    float* Gis = (float*)(smem + OFF_GI);            // [4][1296]
    float* Gcs = (float*)(smem + OFF_GC);            // [4][1024]
    {
        const float4* gi4 = (const float4*)(d_Gi + (size_t)(blockIdx.y * 4) * 1296);
        float4* dsti = (float4*)Gis;
        for (int idx = tid; idx < 4 * 324; idx += 192) dsti[idx] = gi4[idx];
        const float4* gc4 = (const float4*)(d_Gc + (size_t)(blockIdx.x * 4) * 1024);
        float4* dstc = (float4*)Gcs;
        for (int idx = tid; idx < 4 * 256; idx += 192) dstc[idx] = gc4[idx];
    }
    __syncthreads();

    float* misc = (float*)(smem + OFF_MISC);         // per group: 72 floats
    const int g  = tid / 96;                         // group 0/1
    const int t  = tid - g * 96;                     // 0..95
    const int gw = t >> 5;                           // group warp 0..2
    float* irt = misc + g * 72;                      // [36]
    float* iri = irt + 36;                           // [32]
    float* red = irt + 68;                           // [3]

#pragma unroll 1
    for (int it = 0; it < 8; it++) {
        const int pair = g * 8 + it;                 // 0..15
        const int ii = pair >> 2, cc = pair & 3;
        float* Sp = S + (ii * 36) * PS + cc * 32;    // Ss[r][w] = Sp[r*PS+w]
        const float* Gi = Gis + ii * 1296;           // [r*36+x]
        const float* Gc = Gcs + cc * 1024;           // [w*32+x]

        // norms
        if (t < 36) {
            float s0 = 0.f, s1 = 0.f;
#pragma unroll
            for (int w = 0; w < 32; w += 2) {
                float v0 = lrelu(Sp[t * PS + w]);     s0 += v0 * v0;
                float v1 = lrelu(Sp[t * PS + w + 1]); s1 += v1 * v1;
            }
            irt[t] = __fdividef(1.f, sqrtf(s0 + s1) + EPSV);
        } else if (t < 68) {
            int w = t - 36;
            float s0 = 0.f, s1 = 0.f;
#pragma unroll
            for (int r = 0; r < 36; r += 2) {
                float v0 = lrelu(Sp[r * PS + w]);       s0 += v0 * v0;
                float v1 = lrelu(Sp[(r + 1) * PS + w]); s1 += v1 * v1;
            }
            iri[w] = __fdividef(1.f, sqrtf(s0 + s1) + EPSV);
        }
        __syncthreads();

        float val = 0.f;
        if (gw == 0) {
            // ---- t2i: query = word (lane) ----
            const int w = lane;
            float a[36];
            float mx = -1e30f;
#pragma unroll
            for (int r = 0; r < 36; r++) {
                float v = lrelu(Sp[r * PS + w]) * irt[r];
                a[r] = v; mx = fmaxf(mx, v);
            }
            float esum = 0.f;
#pragma unroll
            for (int r = 0; r < 36; r++) { float e = __expf(LAMBDA * (a[r] - mx)); a[r] = e; esum += e; }
            float th = esum * (1.f / 36.f), tsum = 0.f;
#pragma unroll
            for (int r = 0; r < 36; r++) { float v = (a[r] > th) ? a[r] : 0.f; a[r] = v; tsum += v; }
            float inv = __fdividef(1.f, tsum), num = 0.f;
#pragma unroll
            for (int r = 0; r < 36; r++) { a[r] *= inv; num += a[r] * Sp[r * PS + w]; }
            uint64_t a2[18];
#pragma unroll
            for (int q = 0; q < 18; q++) a2[q] = f2pack(a[2 * q], a[2 * q + 1]);
            float den0 = 0.f, den1 = 0.f;
#pragma unroll
            for (int r = 0; r < 36; r += 2) {
                const ulonglong2* Gr0 = (const ulonglong2*)(Gi + r * 36);
                const ulonglong2* Gr1 = (const ulonglong2*)(Gi + (r + 1) * 36);
                uint64_t xa = 0, xb = 0, za = 0, zb = 0;
#pragma unroll
                for (int q = 0; q < 9; q++) {
                    ulonglong2 g0 = Gr0[q], g1 = Gr1[q];
                    ffma2(xa, g0.x, a2[2 * q]);
                    ffma2(xb, g0.y, a2[2 * q + 1]);
                    ffma2(za, g1.x, a2[2 * q]);
                    ffma2(zb, g1.y, a2[2 * q + 1]);
                }
                den0 += a[r] * (f2sum(xa) + f2sum(xb));
                den1 += a[r + 1] * (f2sum(za) + f2sum(zb));
            }
            float den = den0 + den1;
            val = num * __fdividef(1.f,
                  fmaxf(sqrtf(Gc[w * 32 + w]), EPSV) * fmaxf(sqrtf(den), EPSV));
        } else {
            // ---- i2t: query = region ----
            const bool valid = (gw == 1) || (lane < 4);
            const int r = valid ? ((gw == 1) ? lane : 32 + lane) : 35;
            float a[32];
            float mx = -1e30f;
#pragma unroll
            for (int w = 0; w < 32; w++) {
                float v = lrelu(Sp[r * PS + w]) * iri[w];
                a[w] = v; mx = fmaxf(mx, v);
            }
            float esum = 0.f;
#pragma unroll
            for (int w = 0; w < 32; w++) { float e = __expf(LAMBDA * (a[w] - mx)); a[w] = e; esum += e; }
            float th = esum * (1.f / 32.f), tsum = 0.f;
#pragma unroll
            for (int w = 0; w < 32; w++) { float v = (a[w] > th) ? a[w] : 0.f; a[w] = v; tsum += v; }
            float inv = __fdividef(1.f, tsum), num = 0.f;
#pragma unroll
            for (int w = 0; w < 32; w++) { a[w] *= inv; num += a[w] * Sp[r * PS + w]; }
            uint64_t a2[16];
#pragma unroll
            for (int q = 0; q < 16; q++) a2[q] = f2pack(a[2 * q], a[2 * q + 1]);
            float den0 = 0.f, den1 = 0.f;
#pragma unroll
            for (int w = 0; w < 32; w += 2) {
                const ulonglong2* Gr0 = (const ulonglong2*)(Gc + w * 32);
                const ulonglong2* Gr1 = (const ulonglong2*)(Gc + (w + 1) * 32);
                uint64_t xa = 0, xb = 0, za = 0, zb = 0;
#pragma unroll
                for (int q = 0; q < 8; q++) {
                    ulonglong2 g0 = Gr0[q], g1 = Gr1[q];
                    ffma2(xa, g0.x, a2[2 * q]);
                    ffma2(xb, g0.y, a2[2 * q + 1]);
                    ffma2(za, g1.x, a2[2 * q]);
                    ffma2(zb, g1.y, a2[2 * q + 1]);
                }
                den0 += a[w] * (f2sum(xa) + f2sum(xb));
                den1 += a[w + 1] * (f2sum(za) + f2sum(zb));
            }
            float den = den0 + den1;
            float v = num * __fdividef(1.f,
                      fmaxf(sqrtf(Gi[r * 36 + r]), EPSV) * fmaxf(sqrtf(den), EPSV));
            val = valid ? v : 0.f;
        }

#pragma unroll
        for (int off = 16; off > 0; off >>= 1)
            val += __shfl_xor_sync(0xFFFFFFFFu, val, off);
        if (lane == 0) red[gw] = val;
        __syncthreads();
        if (t == 0) {
            int img = blockIdx.y * 4 + ii;
            int cap = blockIdx.x * 4 + cc;
            out[img * N_CAP + cap] = red[0] * (1.f / 32.f) + (red[1] + red[2]) * (1.f / 36.f);
        }
        __syncthreads();   // before next iteration overwrites norms/red
    }
}

// ---------------------------------------------------------------------------
extern "C" void kernel_launch(void* const* d_in, const int* in_sizes, int n_in,
                              void* d_out, int out_size) {
    const float* images   = (const float*)d_in[0];   // (128,36,1024)
    const float* captions = (const float*)d_in[1];   // (128,32,1024)
    float* out = (float*)d_out;                       // (128,128)

    prep_kernel<<<(M_TOT * DIM / 2) / 256, 256>>>(images, M_TOT * DIM / 2, 0);
    prep_kernel<<<(N_TOT * DIM / 2) / 256, 256>>>(captions, N_TOT * DIM / 2, 1);
    gram2_kernel<<<256, 256>>>(images, captions);

    cudaFuncSetAttribute(fused_kernel, cudaFuncAttributeMaxDynamicSharedMemorySize, FSMEM);
    dim3 fgrid(N_TOT / 128, M_TOT / 144);   // (32, 32)
    fused_kernel<<<fgrid, 192, FSMEM>>>(out);
}